// round 3
// baseline (speedup 1.0000x reference)
#include <cuda_runtime.h>
#include <cuda_bf16.h>
#include <math.h>

#define B_SZ 256
#define R_SZ 2048
#define D_SZ 64
#define K_TOP 20

// 2 MB scratch for cosine similarities [B, R]
__device__ float g_sims[B_SZ * R_SZ];

__device__ __forceinline__ unsigned packf(float f) {
    unsigned u = __float_as_uint(f);
    return (u & 0x80000000u) ? ~u : (u | 0x80000000u);
}
__device__ __forceinline__ float unpackf(unsigned p) {
    unsigned b = (p & 0x80000000u) ? (p ^ 0x80000000u) : ~p;
    return __uint_as_float(b);
}
__device__ __forceinline__ unsigned long long kmax64(unsigned long long a,
                                                     unsigned long long b) {
    return a > b ? a : b;
}

// ---------------------------------------------------------------------------
// Kernel 1: fused copy x->out + cosine similarity vs query row.
// Block = 256 threads = 16 rows (all within one batch). Query row cached in
// shared memory once per block (kills the redundant 128MB of L2 q reads).
// ---------------------------------------------------------------------------
__global__ __launch_bounds__(256) void sims_copy_kernel(
    const float* __restrict__ x,
    const int*   __restrict__ qrels,
    float*       __restrict__ out)
{
    __shared__ float4 qsh[16];
    __shared__ float  s_qinv;

    const int tid  = threadIdx.x;
    const int b    = blockIdx.x >> 7;                    // 128 blocks per batch
    const long long base = (long long)blockIdx.x * 16;   // first row of block
    const int qr   = __ldg(&qrels[b]);

    if (tid < 16) {
        const long long qoff = ((long long)b * R_SZ + qr) * D_SZ;
        float4 q = __ldg(reinterpret_cast<const float4*>(x + qoff) + tid);
        qsh[tid] = q;
        float qs = q.x * q.x + q.y * q.y + q.z * q.z + q.w * q.w;
        #pragma unroll
        for (int o = 8; o; o >>= 1) qs += __shfl_xor_sync(0xffffu, qs, o);
        if (tid == 0) s_qinv = 1.0f / fmaxf(sqrtf(qs), 1e-12f);
    }
    __syncthreads();

    const int warp = tid >> 5;
    const int lane = tid & 31;
    const int half = lane >> 4;          // which of the warp's 2 rows
    const int hl   = lane & 15;          // lane within half-warp

    const long long row = base + warp * 2 + half;
    const int r = (int)(row & (R_SZ - 1));

    const float4 v = reinterpret_cast<const float4*>(x + row * D_SZ)[hl];
    reinterpret_cast<float4*>(out + row * D_SZ)[hl] = v;

    const float4 q = qsh[hl];
    float dot = v.x * q.x + v.y * q.y + v.z * q.z + v.w * q.w;
    float ss  = v.x * v.x + v.y * v.y + v.z * v.z + v.w * v.w;

    #pragma unroll
    for (int o = 8; o; o >>= 1) {       // stays within the 16-lane half
        dot += __shfl_xor_sync(0xffffffffu, dot, o);
        ss  += __shfl_xor_sync(0xffffffffu, ss,  o);
    }

    if (hl == 0) {
        float nr = fmaxf(sqrtf(ss), 1e-12f);
        float s  = (dot * s_qinv) / nr;
        if (r == qr) s = -1.0f;          // exclude self
        g_sims[row] = s;
    }
}

// ---------------------------------------------------------------------------
// Kernel 2: per-batch top-20 (register tournament), weighting, query rewrite.
// One block of 256 threads per batch element.
// ---------------------------------------------------------------------------
__global__ __launch_bounds__(256) void topk_enhance_kernel(
    const float* __restrict__ x,
    const int*   __restrict__ qrels,
    const float* __restrict__ thr_raw_p,
    const float* __restrict__ str_raw_p,
    const float* __restrict__ wscale_p,
    const float* __restrict__ temp_p,
    float*       __restrict__ out)
{
    const int b    = blockIdx.x;
    const int tid  = threadIdx.x;
    const int w    = tid >> 5;
    const int lane = tid & 31;

    __shared__ unsigned long long cands[8 * K_TOP];
    __shared__ float topv[K_TOP];
    __shared__ int   topi[K_TOP];
    __shared__ float rinv[K_TOP];
    __shared__ float adj[K_TOP];
    __shared__ float s_strength;
    __shared__ int   s_hasvalid;

    // ---- stage a: each warp extracts its local top-20 of 256 sims --------
    {
        const float* simrow = g_sims + (long long)b * R_SZ + w * 256;
        unsigned long long k[8];
        #pragma unroll
        for (int s = 0; s < 8; ++s) {
            const int local = lane + 32 * s;
            const float v = simrow[local];
            const int idx = w * 256 + local;
            k[s] = ((unsigned long long)packf(v) << 32)
                 | (unsigned)(R_SZ - 1 - idx);      // tie-break: lower idx wins
        }
        for (int it = 0; it < K_TOP; ++it) {
            unsigned long long best = k[0];
            #pragma unroll
            for (int s = 1; s < 8; ++s) best = kmax64(best, k[s]);
            #pragma unroll
            for (int o = 16; o; o >>= 1)
                best = kmax64(best, __shfl_xor_sync(0xffffffffu, best, o));
            // invalidate the winner in its owner's registers
            const int idx   = (R_SZ - 1) - (int)(best & 0xffffffffu);
            const int local = idx - w * 256;
            if ((unsigned)local < 256u && (local & 31) == lane)
                k[local >> 5] = 0ull;
            if (lane == 0) cands[w * K_TOP + it] = best;
        }
    }
    __syncthreads();

    // ---- stage b: warp 0 merges 160 candidates into the global top-20 ----
    if (w == 0) {
        unsigned long long c[5];
        #pragma unroll
        for (int s = 0; s < 5; ++s) {
            const int j = lane + 32 * s;
            c[s] = (j < 8 * K_TOP) ? cands[j] : 0ull;
        }
        for (int it = 0; it < K_TOP; ++it) {
            unsigned long long best = c[0];
            #pragma unroll
            for (int s = 1; s < 5; ++s) best = kmax64(best, c[s]);
            #pragma unroll
            for (int o = 16; o; o >>= 1)
                best = kmax64(best, __shfl_xor_sync(0xffffffffu, best, o));
            #pragma unroll
            for (int s = 0; s < 5; ++s) if (c[s] == best) c[s] = 0ull;  // unique keys
            if (lane == 0) {
                topi[it] = (R_SZ - 1) - (int)(best & 0xffffffffu);
                topv[it] = unpackf((unsigned)(best >> 32));
            }
        }
    }
    __syncthreads();

    // ---- norms of the 20 selected rows ------------------------------------
    {
        for (int k = w; k < K_TOP; k += 8) {
            const float* rp = x + ((long long)b * R_SZ + topi[k]) * D_SZ;
            float2 v = reinterpret_cast<const float2*>(rp)[lane];
            float ssq = v.x * v.x + v.y * v.y;
            #pragma unroll
            for (int o = 16; o; o >>= 1) ssq += __shfl_xor_sync(0xffffffffu, ssq, o);
            if (lane == 0) rinv[k] = 1.0f / fmaxf(sqrtf(ssq), 1e-12f);
        }
    }
    __syncthreads();

    // ---- scalar weighting pipeline (20 elems; single thread) --------------
    if (tid == 0) {
        const float thr      = 1.0f / (1.0f + expf(-thr_raw_p[0]));
        const float strength = 0.2f / (1.0f + expf(-str_raw_p[0]));
        const float tempv    = fminf(fmaxf(temp_p[0], 0.1f), 10.0f);
        const float ws       = wscale_p[0];
        const int   qr       = qrels[b];

        float logits[K_TOP], ev[K_TOP];
        bool  valid[K_TOP];
        float m = -1e9f;
        #pragma unroll
        for (int k = 0; k < K_TOP; ++k) {
            valid[k]  = (topv[k] > thr) && (topi[k] != qr);
            logits[k] = valid[k] ? topv[k] / tempv : -1e9f;
            m = fmaxf(m, logits[k]);
        }
        float se = 0.0f;
        #pragma unroll
        for (int k = 0; k < K_TOP; ++k) { ev[k] = expf(logits[k] - m); se += ev[k]; }

        float suma = 0.0f;
        int hv = 0;
        #pragma unroll
        for (int k = 0; k < K_TOP; ++k) {
            float wgt = valid[k] ? (ev[k] / se) : 0.0f;
            float sw  = 1.0f / (1.0f + expf(-(topv[k] - thr) * 10.0f));
            float a   = wgt * sw * (1.0f + ws * topv[k]);
            adj[k] = a;
            suma  += a;
            hv |= (int)valid[k];
        }
        const float inv = 1.0f / (suma + 1e-8f);
        #pragma unroll
        for (int k = 0; k < K_TOP; ++k) adj[k] *= inv;

        s_strength = strength;
        s_hasvalid = hv;
    }
    __syncthreads();

    // ---- weighted sum of normalized top rows + mix into query row ---------
    if (tid < D_SZ) {
        const int qr = qrels[b];
        const long long qoff = ((long long)b * R_SZ + qr) * D_SZ;
        const float qo = x[qoff + tid];
        float acc = 0.0f;
        #pragma unroll
        for (int k = 0; k < K_TOP; ++k) {
            acc += (adj[k] * rinv[k]) * x[((long long)b * R_SZ + topi[k]) * D_SZ + tid];
        }
        const float s = s_strength;
        out[qoff + tid] = s_hasvalid ? (1.0f - s) * qo + s * acc : qo;
    }
}

// ---------------------------------------------------------------------------
extern "C" void kernel_launch(void* const* d_in, const int* in_sizes, int n_in,
                              void* d_out, int out_size)
{
    const float* x     = (const float*)d_in[0];
    const int*   qrels = (const int*)  d_in[1];
    const float* thr   = (const float*)d_in[2];
    const float* str   = (const float*)d_in[3];
    const float* wsc   = (const float*)d_in[4];
    const float* tmp   = (const float*)d_in[5];
    float* out = (float*)d_out;

    const int blocks1 = (B_SZ * R_SZ) / 16;              // 32768
    sims_copy_kernel<<<blocks1, 256>>>(x, qrels, out);
    topk_enhance_kernel<<<B_SZ, 256>>>(x, qrels, thr, str, wsc, tmp, out);
}

// round 4
// speedup vs baseline: 1.2451x; 1.2451x over previous
#include <cuda_runtime.h>
#include <cuda_bf16.h>
#include <math.h>

#define B_SZ 256
#define R_SZ 2048
#define D_SZ 64
#define K_TOP 20

// Candidate buffers: rows whose cosine sim exceeds the threshold.
__device__ int                g_cnt[B_SZ];
__device__ unsigned long long g_cand[B_SZ * R_SZ];   // 4 MB, worst case all rows

__device__ __forceinline__ unsigned packf(float f) {
    unsigned u = __float_as_uint(f);
    return (u & 0x80000000u) ? ~u : (u | 0x80000000u);
}
__device__ __forceinline__ float unpackf(unsigned p) {
    unsigned b = (p & 0x80000000u) ? (p ^ 0x80000000u) : ~p;
    return __uint_as_float(b);
}

// ---------------------------------------------------------------------------
// Kernel 0: reset candidate counters (deterministic per launch).
// ---------------------------------------------------------------------------
__global__ void zero_cnt_kernel() { g_cnt[threadIdx.x] = 0; }

// ---------------------------------------------------------------------------
// Kernel 1: fused copy x->out + cosine sim vs query row + threshold filter.
// R1 structure: half-warp (16 lanes) per row, q fetched via __ldg in parallel
// with the row load (no barrier serialization).
// ---------------------------------------------------------------------------
__global__ __launch_bounds__(256) void sims_copy_kernel(
    const float* __restrict__ x,
    const int*   __restrict__ qrels,
    const float* __restrict__ thr_raw_p,
    float*       __restrict__ out)
{
    const int warp = (blockIdx.x * blockDim.x + threadIdx.x) >> 5;
    const int lane = threadIdx.x & 31;
    const int half = lane >> 4;          // which of the warp's 2 rows
    const int hl   = lane & 15;          // lane within half-warp

    const long long row = (long long)warp * 2 + half;
    const int b = (int)(row >> 11);                      // R = 2048
    const int r = (int)(row & (R_SZ - 1));
    const int qr = __ldg(&qrels[b]);

    const float4 v = reinterpret_cast<const float4*>(x + row * D_SZ)[hl];

    const long long qrow = ((long long)b * R_SZ + qr) * D_SZ;
    const float4 q = __ldg(reinterpret_cast<const float4*>(x + qrow) + hl);

    // copy row to output (query rows get overwritten by kernel 2 later)
    reinterpret_cast<float4*>(out + row * D_SZ)[hl] = v;

    float dot = v.x * q.x + v.y * q.y + v.z * q.z + v.w * q.w;
    float ss  = v.x * v.x + v.y * v.y + v.z * v.z + v.w * v.w;
    float qs  = q.x * q.x + q.y * q.y + q.z * q.z + q.w * q.w;

    #pragma unroll
    for (int o = 8; o; o >>= 1) {
        dot += __shfl_xor_sync(0xffffffffu, dot, o);
        ss  += __shfl_xor_sync(0xffffffffu, ss,  o);
        qs  += __shfl_xor_sync(0xffffffffu, qs,  o);
    }

    if (hl == 0 && r != qr) {
        const float nr = fmaxf(sqrtf(ss), 1e-12f);
        const float nq = fmaxf(sqrtf(qs), 1e-12f);
        const float s  = dot / (nr * nq);
        const float thr = 1.0f / (1.0f + expf(-__ldg(thr_raw_p)));
        if (s > thr) {
            const int pos = atomicAdd(&g_cnt[b], 1);
            g_cand[(long long)b * R_SZ + pos] =
                ((unsigned long long)packf(s) << 32)
                | (unsigned)(R_SZ - 1 - r);          // tie-break: lower idx wins
        }
    }
}

// ---------------------------------------------------------------------------
// Kernel 2: per-batch select top-min(ncand,20) candidates, weighting, rewrite.
// One block of 256 threads per batch. ncand is typically ~5, so this is tiny,
// but the code is correct for any ncand up to R-1.
// ---------------------------------------------------------------------------
__global__ __launch_bounds__(256) void enhance_kernel(
    const float* __restrict__ x,
    const int*   __restrict__ qrels,
    const float* __restrict__ thr_raw_p,
    const float* __restrict__ str_raw_p,
    const float* __restrict__ wscale_p,
    const float* __restrict__ temp_p,
    float*       __restrict__ out)
{
    const int b    = blockIdx.x;
    const int tid  = threadIdx.x;
    const int w    = tid >> 5;
    const int lane = tid & 31;

    __shared__ unsigned long long sc[R_SZ];     // candidate keys
    __shared__ unsigned long long sred[256];
    __shared__ float topv[K_TOP];
    __shared__ int   topi[K_TOP];
    __shared__ float rinv[K_TOP];
    __shared__ float adj[K_TOP];
    __shared__ float s_strength;
    __shared__ int   s_nsel;

    const int ncand = min(g_cnt[b], R_SZ - 1);
    const int nsel  = min(ncand, K_TOP);
    const unsigned long long* cb = g_cand + (long long)b * R_SZ;
    for (int j = tid; j < ncand; j += 256) sc[j] = cb[j];
    if (tid == 0) s_nsel = nsel;
    __syncthreads();

    // deterministic iterative max-selection (keys are unique)
    for (int it = 0; it < nsel; ++it) {
        unsigned long long best = 0ull;
        for (int j = tid; j < ncand; j += 256)
            if (sc[j] > best) best = sc[j];
        sred[tid] = best;
        __syncthreads();
        #pragma unroll
        for (int o = 128; o; o >>= 1) {
            if (tid < o && sred[tid + o] > sred[tid]) sred[tid] = sred[tid + o];
            __syncthreads();
        }
        best = sred[0];
        for (int j = tid; j < ncand; j += 256)
            if (sc[j] == best) sc[j] = 0ull;
        if (tid == 0) {
            topi[it] = (R_SZ - 1) - (int)(best & 0xffffffffu);
            topv[it] = unpackf((unsigned)(best >> 32));
        }
        __syncthreads();
    }

    // norms of selected rows (warp w handles k = w, w+8, ...)
    for (int k = w; k < nsel; k += 8) {
        const float* rp = x + ((long long)b * R_SZ + topi[k]) * D_SZ;
        float2 v = reinterpret_cast<const float2*>(rp)[lane];
        float ssq = v.x * v.x + v.y * v.y;
        #pragma unroll
        for (int o = 16; o; o >>= 1) ssq += __shfl_xor_sync(0xffffffffu, ssq, o);
        if (lane == 0) rinv[k] = 1.0f / fmaxf(sqrtf(ssq), 1e-12f);
    }
    __syncthreads();

    // scalar weighting pipeline (all entries valid by construction)
    if (tid == 0) {
        const float thr      = 1.0f / (1.0f + expf(-thr_raw_p[0]));
        const float strength = 0.2f / (1.0f + expf(-str_raw_p[0]));
        const float tempv    = fminf(fmaxf(temp_p[0], 0.1f), 10.0f);
        const float ws       = wscale_p[0];

        float m = -1e9f;
        for (int k = 0; k < nsel; ++k) m = fmaxf(m, topv[k] / tempv);
        float se = 0.0f;
        float ev[K_TOP];
        for (int k = 0; k < nsel; ++k) { ev[k] = expf(topv[k] / tempv - m); se += ev[k]; }

        float suma = 0.0f;
        for (int k = 0; k < nsel; ++k) {
            const float wgt = ev[k] / se;
            const float sw  = 1.0f / (1.0f + expf(-(topv[k] - thr) * 10.0f));
            const float a   = wgt * sw * (1.0f + ws * topv[k]);
            adj[k] = a;
            suma  += a;
        }
        const float inv = 1.0f / (suma + 1e-8f);
        for (int k = 0; k < nsel; ++k) adj[k] *= inv;
        s_strength = strength;
    }
    __syncthreads();

    // weighted sum of normalized selected rows + mix into query row
    if (tid < D_SZ) {
        const int qr = qrels[b];
        const long long qoff = ((long long)b * R_SZ + qr) * D_SZ;
        const float qo = x[qoff + tid];
        const int n = s_nsel;
        float acc = 0.0f;
        for (int k = 0; k < n; ++k)
            acc += (adj[k] * rinv[k]) * x[((long long)b * R_SZ + topi[k]) * D_SZ + tid];
        const float s = s_strength;
        out[qoff + tid] = (n > 0) ? (1.0f - s) * qo + s * acc : qo;
    }
}

// ---------------------------------------------------------------------------
extern "C" void kernel_launch(void* const* d_in, const int* in_sizes, int n_in,
                              void* d_out, int out_size)
{
    const float* x     = (const float*)d_in[0];
    const int*   qrels = (const int*)  d_in[1];
    const float* thr   = (const float*)d_in[2];
    const float* str   = (const float*)d_in[3];
    const float* wsc   = (const float*)d_in[4];
    const float* tmp   = (const float*)d_in[5];
    float* out = (float*)d_out;

    zero_cnt_kernel<<<1, B_SZ>>>();
    const int blocks1 = (B_SZ * R_SZ) / 16;              // 32768
    sims_copy_kernel<<<blocks1, 256>>>(x, qrels, thr, out);
    enhance_kernel<<<B_SZ, 256>>>(x, qrels, thr, str, wsc, tmp, out);
}

// round 5
// speedup vs baseline: 1.2520x; 1.0055x over previous
#include <cuda_runtime.h>
#include <cuda_bf16.h>
#include <math.h>

#define B_SZ 256
#define R_SZ 2048
#define D_SZ 64
#define K_TOP 20

// Candidate buffers: rows whose cosine sim exceeds the threshold.
// Zero-initialized at module load; enhance_kernel re-zeros g_cnt after use,
// so every kernel_launch / graph replay starts from a clean state.
__device__ int                g_cnt[B_SZ];
__device__ unsigned long long g_cand[B_SZ * R_SZ];

__device__ __forceinline__ unsigned packf(float f) {
    unsigned u = __float_as_uint(f);
    return (u & 0x80000000u) ? ~u : (u | 0x80000000u);
}
__device__ __forceinline__ float unpackf(unsigned p) {
    unsigned b = (p & 0x80000000u) ? (p ^ 0x80000000u) : ~p;
    return __uint_as_float(b);
}

// ---------------------------------------------------------------------------
// Kernel 1: fused copy x->out + cosine sim vs query row + threshold filter.
// Half-warp (16 lanes) per row. Row stream uses .cs (evict-first) hints;
// q rows stay cache-resident via default __ldg.
// ---------------------------------------------------------------------------
__global__ __launch_bounds__(256) void sims_copy_kernel(
    const float* __restrict__ x,
    const int*   __restrict__ qrels,
    const float* __restrict__ thr_raw_p,
    float*       __restrict__ out)
{
    const int warp = (blockIdx.x * blockDim.x + threadIdx.x) >> 5;
    const int lane = threadIdx.x & 31;
    const int half = lane >> 4;          // which of the warp's 2 rows
    const int hl   = lane & 15;          // lane within half-warp

    const long long row = (long long)warp * 2 + half;
    const int b = (int)(row >> 11);                      // R = 2048
    const int r = (int)(row & (R_SZ - 1));
    const int qr = __ldg(&qrels[b]);

    const float4 v = __ldcs(reinterpret_cast<const float4*>(x + row * D_SZ) + hl);

    const long long qrow = ((long long)b * R_SZ + qr) * D_SZ;
    const float4 q = __ldg(reinterpret_cast<const float4*>(x + qrow) + hl);

    // copy row to output (query rows get overwritten by kernel 2 later)
    __stcs(reinterpret_cast<float4*>(out + row * D_SZ) + hl, v);

    float dot = v.x * q.x + v.y * q.y + v.z * q.z + v.w * q.w;
    float ss  = v.x * v.x + v.y * v.y + v.z * v.z + v.w * v.w;
    float qs  = q.x * q.x + q.y * q.y + q.z * q.z + q.w * q.w;

    #pragma unroll
    for (int o = 8; o; o >>= 1) {
        dot += __shfl_xor_sync(0xffffffffu, dot, o);
        ss  += __shfl_xor_sync(0xffffffffu, ss,  o);
        qs  += __shfl_xor_sync(0xffffffffu, qs,  o);
    }

    if (hl == 0 && r != qr) {
        const float nr = fmaxf(sqrtf(ss), 1e-12f);
        const float nq = fmaxf(sqrtf(qs), 1e-12f);
        const float s  = dot / (nr * nq);
        const float thr = 1.0f / (1.0f + expf(-__ldg(thr_raw_p)));
        if (s > thr) {
            const int pos = atomicAdd(&g_cnt[b], 1);
            g_cand[(long long)b * R_SZ + pos] =
                ((unsigned long long)packf(s) << 32)
                | (unsigned)(R_SZ - 1 - r);          // tie-break: lower idx wins
        }
    }
}

// ---------------------------------------------------------------------------
// Kernel 2: per-batch select top-min(ncand,20), weighting, query-row rewrite.
// One block of 256 threads per batch; warp 0 does the selection with no
// block-wide syncs inside the loop. Also resets g_cnt for the next replay.
// ---------------------------------------------------------------------------
__global__ __launch_bounds__(256) void enhance_kernel(
    const float* __restrict__ x,
    const int*   __restrict__ qrels,
    const float* __restrict__ thr_raw_p,
    const float* __restrict__ str_raw_p,
    const float* __restrict__ wscale_p,
    const float* __restrict__ temp_p,
    float*       __restrict__ out)
{
    const int b    = blockIdx.x;
    const int tid  = threadIdx.x;
    const int w    = tid >> 5;
    const int lane = tid & 31;

    __shared__ int s_ncand;
    __shared__ unsigned long long sc[R_SZ];     // candidate keys (worst case)
    __shared__ float topv[K_TOP];
    __shared__ int   topi[K_TOP];
    __shared__ float rinv[K_TOP];
    __shared__ float adj[K_TOP];
    __shared__ float s_strength;
    __shared__ int   s_nsel;

    if (tid == 0) {
        int c = g_cnt[b];
        g_cnt[b] = 0;                           // reset for next replay
        s_ncand = min(c, R_SZ - 1);
    }
    __syncthreads();

    const int ncand = s_ncand;
    const int nsel  = min(ncand, K_TOP);
    const unsigned long long* cb = g_cand + (long long)b * R_SZ;
    for (int j = tid; j < ncand; j += 256) sc[j] = cb[j];
    if (tid == 0) s_nsel = nsel;
    __syncthreads();

    // warp-0-only deterministic max-selection (keys are unique); ncand ~5
    if (w == 0) {
        for (int it = 0; it < nsel; ++it) {
            unsigned long long best = 0ull;
            for (int j = lane; j < ncand; j += 32)
                if (sc[j] > best) best = sc[j];
            #pragma unroll
            for (int o = 16; o; o >>= 1) {
                unsigned long long t = __shfl_xor_sync(0xffffffffu, best, o);
                if (t > best) best = t;
            }
            for (int j = lane; j < ncand; j += 32)
                if (sc[j] == best) sc[j] = 0ull;
            if (lane == 0) {
                topi[it] = (R_SZ - 1) - (int)(best & 0xffffffffu);
                topv[it] = unpackf((unsigned)(best >> 32));
            }
            __syncwarp();
        }
    }
    __syncthreads();

    // norms of selected rows (warp w handles k = w, w+8, ...)
    for (int k = w; k < nsel; k += 8) {
        const float* rp = x + ((long long)b * R_SZ + topi[k]) * D_SZ;
        float2 v = reinterpret_cast<const float2*>(rp)[lane];
        float ssq = v.x * v.x + v.y * v.y;
        #pragma unroll
        for (int o = 16; o; o >>= 1) ssq += __shfl_xor_sync(0xffffffffu, ssq, o);
        if (lane == 0) rinv[k] = 1.0f / fmaxf(sqrtf(ssq), 1e-12f);
    }
    __syncthreads();

    // scalar weighting pipeline (all entries valid by construction)
    if (tid == 0) {
        const float thr      = 1.0f / (1.0f + expf(-thr_raw_p[0]));
        const float strength = 0.2f / (1.0f + expf(-str_raw_p[0]));
        const float tempv    = fminf(fmaxf(temp_p[0], 0.1f), 10.0f);
        const float ws       = wscale_p[0];

        float m = -1e9f;
        for (int k = 0; k < nsel; ++k) m = fmaxf(m, topv[k] / tempv);
        float se = 0.0f;
        float ev[K_TOP];
        for (int k = 0; k < nsel; ++k) { ev[k] = expf(topv[k] / tempv - m); se += ev[k]; }

        float suma = 0.0f;
        for (int k = 0; k < nsel; ++k) {
            const float wgt = ev[k] / se;
            const float sw  = 1.0f / (1.0f + expf(-(topv[k] - thr) * 10.0f));
            const float a   = wgt * sw * (1.0f + ws * topv[k]);
            adj[k] = a;
            suma  += a;
        }
        const float inv = 1.0f / (suma + 1e-8f);
        for (int k = 0; k < nsel; ++k) adj[k] *= inv;
        s_strength = strength;
    }
    __syncthreads();

    // weighted sum of normalized selected rows + mix into query row
    if (tid < D_SZ) {
        const int qr = qrels[b];
        const long long qoff = ((long long)b * R_SZ + qr) * D_SZ;
        const float qo = x[qoff + tid];
        const int n = s_nsel;
        float acc = 0.0f;
        for (int k = 0; k < n; ++k)
            acc += (adj[k] * rinv[k]) * x[((long long)b * R_SZ + topi[k]) * D_SZ + tid];
        const float s = s_strength;
        out[qoff + tid] = (n > 0) ? (1.0f - s) * qo + s * acc : qo;
    }
}

// ---------------------------------------------------------------------------
extern "C" void kernel_launch(void* const* d_in, const int* in_sizes, int n_in,
                              void* d_out, int out_size)
{
    const float* x     = (const float*)d_in[0];
    const int*   qrels = (const int*)  d_in[1];
    const float* thr   = (const float*)d_in[2];
    const float* str   = (const float*)d_in[3];
    const float* wsc   = (const float*)d_in[4];
    const float* tmp   = (const float*)d_in[5];
    float* out = (float*)d_out;

    const int blocks1 = (B_SZ * R_SZ) / 16;              // 32768
    sims_copy_kernel<<<blocks1, 256>>>(x, qrels, thr, out);
    enhance_kernel<<<B_SZ, 256>>>(x, qrels, thr, str, wsc, tmp, out);
}

// round 6
// speedup vs baseline: 1.4446x; 1.1538x over previous
#include <cuda_runtime.h>
#include <cuda_bf16.h>
#include <math.h>

#define B_SZ 256
#define R_SZ 2048
#define D_SZ 64
#define K_TOP 20

// Candidate state. Zero-initialized at load; enhance_kernel re-zeros g_cnt
// after consuming it, so every launch/graph replay starts clean.
__device__ int                g_cnt[B_SZ];
__device__ unsigned long long g_cand[B_SZ * R_SZ];
__device__ float              g_rinv[B_SZ * R_SZ];

__device__ __forceinline__ unsigned packf(float f) {
    unsigned u = __float_as_uint(f);
    return (u & 0x80000000u) ? ~u : (u | 0x80000000u);
}
__device__ __forceinline__ float unpackf(unsigned p) {
    unsigned b = (p & 0x80000000u) ? (p ^ 0x80000000u) : ~p;
    return __uint_as_float(b);
}

// ---------------------------------------------------------------------------
// Kernel 1: fused copy x->out + cosine sim + threshold filter + rinv stash.
// Warp handles 4 consecutive rows (2 per half-warp) for higher MLP; q row
// loaded once per thread and shared by both rows.
// ---------------------------------------------------------------------------
__global__ __launch_bounds__(256) void sims_copy_kernel(
    const float* __restrict__ x,
    const int*   __restrict__ qrels,
    const float* __restrict__ thr_raw_p,
    float*       __restrict__ out)
{
    const int gw   = (blockIdx.x * blockDim.x + threadIdx.x) >> 5;
    const int lane = threadIdx.x & 31;
    const int half = lane >> 4;
    const int hl   = lane & 15;

    const long long base = (long long)gw * 4;         // 4 rows per warp
    const long long rowA = base + half * 2;
    const long long rowB = rowA + 1;
    const int b  = (int)(base >> 11);                  // R = 2048, groups of 4 never cross batch
    const int qr = __ldg(&qrels[b]);

    const float4 vA = __ldcs(reinterpret_cast<const float4*>(x + rowA * D_SZ) + hl);
    const float4 vB = __ldcs(reinterpret_cast<const float4*>(x + rowB * D_SZ) + hl);
    const long long qrow = ((long long)b * R_SZ + qr) * D_SZ;
    const float4 q = __ldg(reinterpret_cast<const float4*>(x + qrow) + hl);

    __stcs(reinterpret_cast<float4*>(out + rowA * D_SZ) + hl, vA);
    __stcs(reinterpret_cast<float4*>(out + rowB * D_SZ) + hl, vB);

    float dotA = vA.x * q.x + vA.y * q.y + vA.z * q.z + vA.w * q.w;
    float ssA  = vA.x * vA.x + vA.y * vA.y + vA.z * vA.z + vA.w * vA.w;
    float dotB = vB.x * q.x + vB.y * q.y + vB.z * q.z + vB.w * q.w;
    float ssB  = vB.x * vB.x + vB.y * vB.y + vB.z * vB.z + vB.w * vB.w;
    float qs   = q.x * q.x + q.y * q.y + q.z * q.z + q.w * q.w;

    #pragma unroll
    for (int o = 8; o; o >>= 1) {       // stays within each 16-lane half
        dotA += __shfl_xor_sync(0xffffffffu, dotA, o);
        ssA  += __shfl_xor_sync(0xffffffffu, ssA,  o);
        dotB += __shfl_xor_sync(0xffffffffu, dotB, o);
        ssB  += __shfl_xor_sync(0xffffffffu, ssB,  o);
        qs   += __shfl_xor_sync(0xffffffffu, qs,   o);
    }

    if (hl == 0) {
        const float nqi = 1.0f / fmaxf(sqrtf(qs), 1e-12f);
        const float thr = 1.0f / (1.0f + expf(-__ldg(thr_raw_p)));
        const int rA = (int)(rowA & (R_SZ - 1));
        const int rB = rA + 1;

        const float nrA = fmaxf(sqrtf(ssA), 1e-12f);
        const float sA  = dotA * nqi / nrA;
        if (rA != qr && sA > thr) {
            const int pos = atomicAdd(&g_cnt[b], 1);
            const long long o = (long long)b * R_SZ + pos;
            g_cand[o] = ((unsigned long long)packf(sA) << 32)
                      | (unsigned)(R_SZ - 1 - rA);
            g_rinv[o] = 1.0f / nrA;
        }
        const float nrB = fmaxf(sqrtf(ssB), 1e-12f);
        const float sB  = dotB * nqi / nrB;
        if (rB != qr && sB > thr) {
            const int pos = atomicAdd(&g_cnt[b], 1);
            const long long o = (long long)b * R_SZ + pos;
            g_cand[o] = ((unsigned long long)packf(sB) << 32)
                      | (unsigned)(R_SZ - 1 - rB);
            g_rinv[o] = 1.0f / nrB;
        }
    }
}

// ---------------------------------------------------------------------------
// Kernel 2: per-batch top-min(ncand,20) + weighting + query-row rewrite.
// One 64-thread block per batch. Selection is a mutation-free descending
// unique-key scan in warp 0 (keys strictly below the previous pick).
// ---------------------------------------------------------------------------
__global__ __launch_bounds__(64) void enhance_kernel(
    const float* __restrict__ x,
    const int*   __restrict__ qrels,
    const float* __restrict__ thr_raw_p,
    const float* __restrict__ str_raw_p,
    const float* __restrict__ wscale_p,
    const float* __restrict__ temp_p,
    float*       __restrict__ out)
{
    const int b    = blockIdx.x;
    const int tid  = threadIdx.x;
    const int lane = tid & 31;

    __shared__ float topv[K_TOP];
    __shared__ int   topi[K_TOP];
    __shared__ int   spos[K_TOP];
    __shared__ float srin[K_TOP];
    __shared__ float adj[K_TOP];
    __shared__ float s_strength;
    __shared__ int   s_nsel;

    const unsigned long long* cb = g_cand + (long long)b * R_SZ;

    if (tid < 32) {
        // one parallel round trip: count + first 128 candidate keys
        int c = 0;
        if (lane == 0) { c = g_cnt[b]; g_cnt[b] = 0; }
        unsigned long long k0 = cb[lane];
        unsigned long long k1 = cb[lane + 32];
        unsigned long long k2 = cb[lane + 64];
        unsigned long long k3 = cb[lane + 96];
        const int ncand = min(__shfl_sync(0xffffffffu, c, 0), R_SZ - 1);
        const int nsel  = min(ncand, K_TOP);
        if (lane == 0) s_nsel = nsel;

        if ((lane)      >= ncand) k0 = 0ull;
        if ((lane + 32) >= ncand) k1 = 0ull;
        if ((lane + 64) >= ncand) k2 = 0ull;
        if ((lane + 96) >= ncand) k3 = 0ull;

        unsigned long long prev = ~0ull;
        for (int it = 0; it < nsel; ++it) {
            unsigned long long lb = 0ull; int lp = -1;
            if (k0 < prev && k0 > lb) { lb = k0; lp = lane; }
            if (k1 < prev && k1 > lb) { lb = k1; lp = lane + 32; }
            if (k2 < prev && k2 > lb) { lb = k2; lp = lane + 64; }
            if (k3 < prev && k3 > lb) { lb = k3; lp = lane + 96; }
            for (int j = 128 + lane; j < ncand; j += 32) {     // cold path
                unsigned long long k = cb[j];
                if (k < prev && k > lb) { lb = k; lp = j; }
            }
            #pragma unroll
            for (int o = 16; o; o >>= 1) {
                unsigned long long ok = __shfl_xor_sync(0xffffffffu, lb, o);
                int op = __shfl_xor_sync(0xffffffffu, lp, o);
                if (ok > lb) { lb = ok; lp = op; }
            }
            prev = lb;
            if (lane == 0) {
                topi[it] = (R_SZ - 1) - (int)(lb & 0xffffffffu);
                topv[it] = unpackf((unsigned)(lb >> 32));
                spos[it] = lp;
            }
        }
    }
    __syncthreads();

    const int nsel = s_nsel;
    if (tid < nsel) srin[tid] = g_rinv[(long long)b * R_SZ + spos[tid]];

    if (tid == 0) {
        const float thr      = 1.0f / (1.0f + expf(-thr_raw_p[0]));
        const float strength = 0.2f / (1.0f + expf(-str_raw_p[0]));
        const float tempv    = fminf(fmaxf(temp_p[0], 0.1f), 10.0f);
        const float ws       = wscale_p[0];

        float m = -1e9f;
        for (int k = 0; k < nsel; ++k) m = fmaxf(m, topv[k] / tempv);
        float se = 0.0f;
        float ev[K_TOP];
        for (int k = 0; k < nsel; ++k) { ev[k] = expf(topv[k] / tempv - m); se += ev[k]; }

        float suma = 0.0f;
        for (int k = 0; k < nsel; ++k) {
            const float wgt = ev[k] / se;
            const float sw  = 1.0f / (1.0f + expf(-(topv[k] - thr) * 10.0f));
            const float a   = wgt * sw * (1.0f + ws * topv[k]);
            adj[k] = a;
            suma  += a;
        }
        const float inv = 1.0f / (suma + 1e-8f);
        for (int k = 0; k < nsel; ++k) adj[k] *= inv;
        s_strength = strength;
    }
    __syncthreads();

    // weighted sum of normalized selected rows + mix into query row
    {
        const int qr = __ldg(&qrels[b]);
        const long long qoff = ((long long)b * R_SZ + qr) * D_SZ;
        const float qo = x[qoff + tid];
        float acc = 0.0f;
        for (int k = 0; k < nsel; ++k)
            acc += (adj[k] * srin[k]) * x[((long long)b * R_SZ + topi[k]) * D_SZ + tid];
        const float s = s_strength;
        out[qoff + tid] = (nsel > 0) ? (1.0f - s) * qo + s * acc : qo;
    }
}

// ---------------------------------------------------------------------------
extern "C" void kernel_launch(void* const* d_in, const int* in_sizes, int n_in,
                              void* d_out, int out_size)
{
    const float* x     = (const float*)d_in[0];
    const int*   qrels = (const int*)  d_in[1];
    const float* thr   = (const float*)d_in[2];
    const float* str   = (const float*)d_in[3];
    const float* wsc   = (const float*)d_in[4];
    const float* tmp   = (const float*)d_in[5];
    float* out = (float*)d_out;

    const int blocks1 = (B_SZ * R_SZ) / 32;              // 4 rows/warp * 8 warps
    sims_copy_kernel<<<blocks1, 256>>>(x, qrels, thr, out);
    enhance_kernel<<<B_SZ, 64>>>(x, qrels, thr, str, wsc, tmp, out);
}